// round 1
// baseline (speedup 1.0000x reference)
#include <cuda_runtime.h>
#include <math.h>

#define TT 256
#define BB 64
#define DD 1024
#define ND 3072          // 3*D
#define MM (TT*BB)       // 16384

// Scratch (no cudaMalloc allowed): x_proj [T,B,3D] fp32 = 201 MB, h double buffer.
__device__ float g_xproj[(size_t)MM * ND];
__device__ float g_h[2][BB * DD];

// ---------------------------------------------------------------------------
// x_proj GEMM: C[M,N] = A[M,K] * W[K,N] + bias[N]
// M=16384, K=1024, N=3072. Tile 128x64, k-chunk 32, 256 threads, 8x4 microtile.
// ---------------------------------------------------------------------------
__global__ void gemm_xproj(const float* __restrict__ A,
                           const float* __restrict__ W,
                           const float* __restrict__ bias) {
    __shared__ float As[128][36];   // padded: row stride 144B (16B aligned)
    __shared__ float Bs[32][64];

    const int tid = threadIdx.x;
    const int bm = blockIdx.y * 128;
    const int bn = blockIdx.x * 64;
    const int ty = tid >> 4;        // 0..15 -> 8 rows each
    const int tx = tid & 15;        // 0..15 -> 4 cols each

    float acc[8][4];
    #pragma unroll
    for (int i = 0; i < 8; i++)
        #pragma unroll
        for (int j = 0; j < 4; j++) acc[i][j] = 0.f;

    for (int k0 = 0; k0 < DD; k0 += 32) {
        // A tile 128x32 = 1024 float4, 4 per thread
        #pragma unroll
        for (int l = 0; l < 4; l++) {
            int e  = tid + l * 256;     // float4 index
            int r  = e >> 3;            // 0..127
            int c4 = e & 7;             // 0..7
            float4 v = *(const float4*)&A[(size_t)(bm + r) * DD + k0 + c4 * 4];
            *(float4*)&As[r][c4 * 4] = v;
        }
        // B tile 32x64 = 512 float4, 2 per thread
        #pragma unroll
        for (int l = 0; l < 2; l++) {
            int e  = tid + l * 256;
            int r  = e >> 4;            // 0..31
            int c4 = e & 15;            // 0..15
            *(float4*)&Bs[r][c4 * 4] =
                *(const float4*)&W[(size_t)(k0 + r) * ND + bn + c4 * 4];
        }
        __syncthreads();

        #pragma unroll
        for (int kk = 0; kk < 32; kk++) {
            float4 bv = *(const float4*)&Bs[kk][tx * 4];
            float b4[4] = {bv.x, bv.y, bv.z, bv.w};
            #pragma unroll
            for (int i = 0; i < 8; i++) {
                float a = As[ty * 8 + i][kk];
                acc[i][0] += a * b4[0];
                acc[i][1] += a * b4[1];
                acc[i][2] += a * b4[2];
                acc[i][3] += a * b4[3];
            }
        }
        __syncthreads();
    }

    #pragma unroll
    for (int i = 0; i < 8; i++) {
        int m = bm + ty * 8 + i;
        #pragma unroll
        for (int j = 0; j < 4; j++) {
            int n = bn + tx * 4 + j;
            g_xproj[(size_t)m * ND + n] = acc[i][j] + bias[n];
        }
    }
}

// ---------------------------------------------------------------------------
// One GRU step. Block = 8 output columns (d) x all 64 batch rows. Grid = 128.
// 256 threads: thread owns (d = d0 + tid%8) and batch rows {tid/8, tid/8+32}.
// ---------------------------------------------------------------------------
__global__ void gru_step(int t,
                         const float* __restrict__ hiddens,
                         const int*   __restrict__ dones,
                         const float* __restrict__ init_carry,
                         const float* __restrict__ W_h,
                         const float* __restrict__ b_hn,
                         float* __restrict__ out) {
    __shared__ float Hs[64][36];    // h_eff tile, padded (row stride 144B)
    __shared__ float Ws[32][24];    // W chunk: [kk][gate*8 + d_local]
    __shared__ unsigned char sdone[64];

    const int tid = threadIdx.x;
    const int d0  = blockIdx.x * 8;
    const int dl  = tid & 7;
    const int b0  = tid >> 3;       // 0..31
    const int d   = d0 + dl;

    const float* hprev = (t == 0) ? init_carry : g_h[t & 1];
    float* hnext = g_h[(t + 1) & 1];

    if (tid < 64) sdone[tid] = (dones[t * BB + tid] != 0) ? 1 : 0;
    __syncthreads();

    float ar0 = 0.f, az0 = 0.f, an0 = 0.f;
    float ar1 = 0.f, az1 = 0.f, an1 = 0.f;

    for (int k0 = 0; k0 < DD; k0 += 32) {
        // h_eff tile 64x32 = 512 float4, 2 per thread (done-masked)
        #pragma unroll
        for (int l = 0; l < 2; l++) {
            int e  = tid + l * 256;
            int r  = e >> 3;        // 0..63
            int c4 = e & 7;
            const float* src = sdone[r] ? &hiddens[((size_t)t * BB + r) * DD]
                                        : &hprev[(size_t)r * DD];
            float4 v = *(const float4*)&src[k0 + c4 * 4];
            *(float4*)&Hs[r][c4 * 4] = v;
        }
        // W chunk: 32 rows x 24 cols = 768 floats, 3 per thread
        #pragma unroll
        for (int l = 0; l < 3; l++) {
            int e  = tid + l * 256;     // 0..767
            int kk = e / 24;
            int c  = e % 24;
            int g  = c >> 3;            // gate 0..2
            int dd = c & 7;
            Ws[kk][c] = W_h[(size_t)(k0 + kk) * ND + g * DD + d0 + dd];
        }
        __syncthreads();

        #pragma unroll
        for (int kk = 0; kk < 32; kk++) {
            float wr = Ws[kk][dl];
            float wz = Ws[kk][8 + dl];
            float wn = Ws[kk][16 + dl];
            float h0 = Hs[b0][kk];
            float h1 = Hs[b0 + 32][kk];
            ar0 += h0 * wr; az0 += h0 * wz; an0 += h0 * wn;
            ar1 += h1 * wr; az1 += h1 * wz; an1 += h1 * wn;
        }
        __syncthreads();
    }

    const float bh = b_hn[d];

    #pragma unroll
    for (int half = 0; half < 2; half++) {
        int b = b0 + half * 32;
        float accr = half ? ar1 : ar0;
        float accz = half ? az1 : az0;
        float accn = half ? an1 : an0;

        size_t tb   = (size_t)t * BB + b;
        size_t base = tb * DD + d;
        float xr = g_xproj[tb * ND + d];
        float xz = g_xproj[tb * ND + DD + d];
        float xn = g_xproj[tb * ND + 2 * DD + d];
        float he = sdone[b] ? hiddens[base] : hprev[(size_t)b * DD + d];

        float r = 1.f / (1.f + expf(-(xr + accr)));
        float z = 1.f / (1.f + expf(-(xz + accz)));
        float n = tanhf(xn + r * (accn + bh));
        float hn = (1.f - z) * n + z * he;

        hnext[(size_t)b * DD + d] = hn;
        out[(size_t)BB * DD + base] = hn;          // ys[t, b, d]
        if (t == TT - 1) out[(size_t)b * DD + d] = hn;  // final_carry
    }
}

// ---------------------------------------------------------------------------
extern "C" void kernel_launch(void* const* d_in, const int* in_sizes, int n_in,
                              void* d_out, int out_size) {
    const float* ins        = (const float*)d_in[0];
    const float* hiddens    = (const float*)d_in[1];
    const int*   dones      = (const int*)d_in[2];
    const float* init_carry = (const float*)d_in[3];
    const float* W_i        = (const float*)d_in[4];
    const float* W_h        = (const float*)d_in[5];
    const float* b_i        = (const float*)d_in[6];
    const float* b_hn       = (const float*)d_in[7];
    float* out = (float*)d_out;

    dim3 grid_gemm(ND / 64, MM / 128);   // 48 x 128
    gemm_xproj<<<grid_gemm, 256>>>(ins, W_i, b_i);

    for (int t = 0; t < TT; t++) {
        gru_step<<<128, 256>>>(t, hiddens, dones, init_carry, W_h, b_hn, out);
    }
}

// round 2
// speedup vs baseline: 1.5536x; 1.5536x over previous
#include <cuda_runtime.h>
#include <math.h>

#define TT 256
#define BB 64
#define DD 1024
#define ND 3072          // 3*D
#define MM (TT*BB)       // 16384

// Scratch (no cudaMalloc allowed)
__device__ float g_xproj[(size_t)MM * ND];   // [T*B, 3D]
__device__ float g_h[2][BB * DD];            // h double buffer

__device__ __forceinline__ float to_tf32(float x) {
    float y;
    asm("cvt.rna.tf32.f32 %0, %1;" : "=f"(y) : "f"(x));
    return y;
}

__device__ __forceinline__ void mma_tf32(float d[4], const unsigned a[4], const unsigned b[2]) {
    asm volatile("mma.sync.aligned.m16n8k8.row.col.f32.tf32.tf32.f32 "
                 "{%0,%1,%2,%3}, {%4,%5,%6,%7}, {%8,%9}, {%0,%1,%2,%3};"
                 : "+f"(d[0]), "+f"(d[1]), "+f"(d[2]), "+f"(d[3])
                 : "r"(a[0]), "r"(a[1]), "r"(a[2]), "r"(a[3]),
                   "r"(b[0]), "r"(b[1]));
}

// ---------------------------------------------------------------------------
// x_proj GEMM (tf32 tensor cores): C[M,N] = A[M,K]*W[K,N] + bias
// Block tile 128m x 64n, k-chunk 32. 256 threads = 8 warps in 4m x 2n grid,
// warp tile 32m x 32n = 2x4 m16n8 tiles.
// ---------------------------------------------------------------------------
__global__ void gemm_xproj(const float* __restrict__ A,
                           const float* __restrict__ W,
                           const float* __restrict__ bias) {
    __shared__ float As[128 * 36];   // stride 36 (pad 4)
    __shared__ float Bs[32 * 72];    // stride 72 (pad 8)

    const int tid  = threadIdx.x;
    const int w    = tid >> 5;
    const int lane = tid & 31;
    const int q    = lane >> 2;      // groupID
    const int tg   = lane & 3;       // thread-in-group
    const int wm   = w >> 1;         // 0..3
    const int wn   = w & 1;          // 0..1
    const int bm   = blockIdx.y * 128;
    const int bn   = blockIdx.x * 64;

    float acc[8][4];
    #pragma unroll
    for (int i = 0; i < 8; i++)
        #pragma unroll
        for (int j = 0; j < 4; j++) acc[i][j] = 0.f;

    for (int kc = 0; kc < DD; kc += 32) {
        // A tile 128x32 = 1024 float4, 4 per thread
        #pragma unroll
        for (int l = 0; l < 4; l++) {
            int e  = tid + l * 256;
            int r  = e >> 3;
            int c4 = e & 7;
            float4 v = *(const float4*)&A[(size_t)(bm + r) * DD + kc + c4 * 4];
            float* dst = &As[r * 36 + c4 * 4];
            dst[0] = to_tf32(v.x); dst[1] = to_tf32(v.y);
            dst[2] = to_tf32(v.z); dst[3] = to_tf32(v.w);
        }
        // B tile 32x64 = 512 float4, 2 per thread
        #pragma unroll
        for (int l = 0; l < 2; l++) {
            int e  = tid + l * 256;
            int r  = e >> 4;
            int c4 = e & 15;
            float4 v = *(const float4*)&W[(size_t)(kc + r) * ND + bn + c4 * 4];
            float* dst = &Bs[r * 72 + c4 * 4];
            dst[0] = to_tf32(v.x); dst[1] = to_tf32(v.y);
            dst[2] = to_tf32(v.z); dst[3] = to_tf32(v.w);
        }
        __syncthreads();

        #pragma unroll
        for (int ks = 0; ks < 4; ks++) {
            const int koff = ks * 8;
            unsigned a[2][4];
            #pragma unroll
            for (int mt = 0; mt < 2; mt++) {
                int r0 = wm * 32 + mt * 16 + q;
                a[mt][0] = __float_as_uint(As[r0 * 36 + koff + tg]);
                a[mt][1] = __float_as_uint(As[(r0 + 8) * 36 + koff + tg]);
                a[mt][2] = __float_as_uint(As[r0 * 36 + koff + tg + 4]);
                a[mt][3] = __float_as_uint(As[(r0 + 8) * 36 + koff + tg + 4]);
            }
            #pragma unroll
            for (int nt = 0; nt < 4; nt++) {
                int n = wn * 32 + nt * 8 + q;
                unsigned b[2];
                b[0] = __float_as_uint(Bs[(koff + tg) * 72 + n]);
                b[1] = __float_as_uint(Bs[(koff + tg + 4) * 72 + n]);
                mma_tf32(acc[0 * 4 + nt], a[0], b);
                mma_tf32(acc[1 * 4 + nt], a[1], b);
            }
        }
        __syncthreads();
    }

    // Epilogue: add bias, write g_xproj
    #pragma unroll
    for (int mt = 0; mt < 2; mt++) {
        int row = bm + wm * 32 + mt * 16 + q;
        #pragma unroll
        for (int nt = 0; nt < 4; nt++) {
            int col = bn + wn * 32 + nt * 8 + 2 * tg;
            float b0 = bias[col], b1 = bias[col + 1];
            float* c = acc[mt * 4 + nt];
            g_xproj[(size_t)row * ND + col]           = c[0] + b0;
            g_xproj[(size_t)row * ND + col + 1]       = c[1] + b1;
            g_xproj[(size_t)(row + 8) * ND + col]     = c[2] + b0;
            g_xproj[(size_t)(row + 8) * ND + col + 1] = c[3] + b1;
        }
    }
}

// ---------------------------------------------------------------------------
// One GRU step (tf32 tensor cores). Grid = 128 blocks; block owns 8 d-columns
// => 24 gate columns (r,z,n). 8 warps k-split K=1024; within each 64-wide
// k-chunk warp w handles the 8-wide k-step at offset w*8.
// 12 m16n8 tiles per warp (4 m-tiles over batch=64, 3 n-tiles over 24 cols).
// 2-phase smem reduction over the 8 warp partials, then fused gate epilogue.
// ---------------------------------------------------------------------------
__global__ void gru_step(int t,
                         const float* __restrict__ hiddens,
                         const int*   __restrict__ dones,
                         const float* __restrict__ init_carry,
                         const float* __restrict__ W_h,
                         const float* __restrict__ b_hn,
                         float* __restrict__ out) {
    __shared__ float Hs[64 * 68];        // h_eff chunk [64][64], stride 68
    __shared__ float Ws[64 * 24];        // W chunk [64k][24 cols], stride 24
    __shared__ float Red[4 * 64 * 24];   // 4 reduction slabs
    __shared__ unsigned char sdone[64];

    const int tid  = threadIdx.x;
    const int w    = tid >> 5;
    const int lane = tid & 31;
    const int q    = lane >> 2;
    const int tg   = lane & 3;
    const int d0   = blockIdx.x * 8;
    const int koff = w * 8;              // warp's k-step inside each chunk

    const float* hprev = (t == 0) ? init_carry : g_h[t & 1];
    float* hnext = g_h[(t + 1) & 1];

    if (tid < 64) sdone[tid] = (dones[t * BB + tid] != 0) ? 1 : 0;
    __syncthreads();

    float acc[12][4];   // tiles (mt 0..3, nt 0..2) -> idx mt*3+nt
    #pragma unroll
    for (int i = 0; i < 12; i++)
        #pragma unroll
        for (int j = 0; j < 4; j++) acc[i][j] = 0.f;

    for (int kc = 0; kc < DD; kc += 64) {
        // h_eff chunk: 64 rows x 64 k = 1024 float4, 4 per thread (done-masked)
        #pragma unroll
        for (int l = 0; l < 4; l++) {
            int e  = tid + l * 256;
            int r  = e >> 4;        // 0..63 (batch row)
            int c4 = e & 15;
            const float* src = sdone[r] ? &hiddens[((size_t)t * BB + r) * DD]
                                        : &hprev[(size_t)r * DD];
            float4 v = *(const float4*)&src[kc + c4 * 4];
            float* dst = &Hs[r * 68 + c4 * 4];
            dst[0] = to_tf32(v.x); dst[1] = to_tf32(v.y);
            dst[2] = to_tf32(v.z); dst[3] = to_tf32(v.w);
        }
        // W chunk: 64 k-rows x 24 cols = 1536 floats, 6 per thread
        #pragma unroll
        for (int l = 0; l < 6; l++) {
            int e  = tid + l * 256;
            int k  = e / 24;
            int c  = e - k * 24;
            int g  = c >> 3;
            int di = c & 7;
            Ws[k * 24 + c] = to_tf32(W_h[(size_t)(kc + k) * ND + g * DD + d0 + di]);
        }
        __syncthreads();

        // one k-step (8 k) per warp in this chunk
        unsigned a[4][4];
        #pragma unroll
        for (int mt = 0; mt < 4; mt++) {
            int r0 = mt * 16 + q;
            a[mt][0] = __float_as_uint(Hs[r0 * 68 + koff + tg]);
            a[mt][1] = __float_as_uint(Hs[(r0 + 8) * 68 + koff + tg]);
            a[mt][2] = __float_as_uint(Hs[r0 * 68 + koff + tg + 4]);
            a[mt][3] = __float_as_uint(Hs[(r0 + 8) * 68 + koff + tg + 4]);
        }
        #pragma unroll
        for (int nt = 0; nt < 3; nt++) {
            unsigned b[2];
            b[0] = __float_as_uint(Ws[(koff + tg) * 24 + nt * 8 + q]);
            b[1] = __float_as_uint(Ws[(koff + tg + 4) * 24 + nt * 8 + q]);
            #pragma unroll
            for (int mt = 0; mt < 4; mt++)
                mma_tf32(acc[mt * 3 + nt], a[mt], b);
        }
        __syncthreads();
    }

    // ---- reduction: 8 warp partials -> 4 slabs -> sum ----
    float* slab = &Red[(w & 3) * 1536];
    if (w >= 4) {
        #pragma unroll
        for (int tI = 0; tI < 12; tI++) {
            int mt = tI / 3, nt = tI - mt * 3;
            int base = (mt * 16 + q) * 24 + nt * 8 + 2 * tg;
            slab[base]           = acc[tI][0];
            slab[base + 1]       = acc[tI][1];
            slab[base + 192]     = acc[tI][2];   // +8 rows
            slab[base + 193]     = acc[tI][3];
        }
    }
    __syncthreads();
    if (w < 4) {
        #pragma unroll
        for (int tI = 0; tI < 12; tI++) {
            int mt = tI / 3, nt = tI - mt * 3;
            int base = (mt * 16 + q) * 24 + nt * 8 + 2 * tg;
            slab[base]       += acc[tI][0];
            slab[base + 1]   += acc[tI][1];
            slab[base + 192] += acc[tI][2];
            slab[base + 193] += acc[tI][3];
        }
    }
    __syncthreads();

    // ---- gate epilogue: 512 (b,d) pairs, 2 per thread ----
    #pragma unroll
    for (int pi = 0; pi < 2; pi++) {
        int pp = tid * 2 + pi;
        int b  = pp >> 3;
        int di = pp & 7;
        int d  = d0 + di;

        float sr = 0.f, sz = 0.f, sn = 0.f;
        #pragma unroll
        for (int s = 0; s < 4; s++) {
            const float* rb = &Red[s * 1536 + b * 24];
            sr += rb[di];
            sz += rb[8 + di];
            sn += rb[16 + di];
        }

        size_t tb   = (size_t)t * BB + b;
        size_t base = tb * DD + d;
        float xr = g_xproj[tb * ND + d];
        float xz = g_xproj[tb * ND + DD + d];
        float xn = g_xproj[tb * ND + 2 * DD + d];
        float he = sdone[b] ? hiddens[base] : hprev[(size_t)b * DD + d];

        float r = 1.f / (1.f + __expf(-(xr + sr)));
        float z = 1.f / (1.f + __expf(-(xz + sz)));
        float n = tanhf(xn + r * (sn + b_hn[d]));
        float hn = (1.f - z) * n + z * he;

        hnext[(size_t)b * DD + d] = hn;
        out[(size_t)BB * DD + base] = hn;              // ys[t,b,d]
        if (t == TT - 1) out[(size_t)b * DD + d] = hn; // final_carry
    }
}

// ---------------------------------------------------------------------------
extern "C" void kernel_launch(void* const* d_in, const int* in_sizes, int n_in,
                              void* d_out, int out_size) {
    const float* ins        = (const float*)d_in[0];
    const float* hiddens    = (const float*)d_in[1];
    const int*   dones      = (const int*)d_in[2];
    const float* init_carry = (const float*)d_in[3];
    const float* W_i        = (const float*)d_in[4];
    const float* W_h        = (const float*)d_in[5];
    const float* b_i        = (const float*)d_in[6];
    const float* b_hn       = (const float*)d_in[7];
    float* out = (float*)d_out;

    dim3 grid_gemm(ND / 64, MM / 128);   // 48 x 128
    gemm_xproj<<<grid_gemm, 256>>>(ins, W_i, b_i);

    for (int t = 0; t < TT; t++) {
        gru_step<<<128, 256>>>(t, hiddens, dones, init_carry, W_h, b_hn, out);
    }
}

// round 4
// speedup vs baseline: 4.7389x; 3.0502x over previous
#include <cuda_runtime.h>
#include <math.h>
#include <stdint.h>

#define TT 256
#define BB 64
#define DD 1024
#define ND 3072          // 3*D
#define MM (TT*BB)       // 16384
#define NBLK 128

// Device scratch (no cudaMalloc allowed)
__device__ float g_xproj[(size_t)MM * ND];        // [T*B, 3D]
__device__ float g_h[2][BB * DD];                 // exact h ping-pong
__device__ float g_h32[2][BB * DD];               // tf32-rounded h ping-pong (MMA path)
__device__ float g_hid32[(size_t)TT * BB * DD];   // tf32-rounded hiddens
__device__ float g_ic32[BB * DD];                 // tf32-rounded init_carry
__device__ unsigned g_ctr;                        // grid barrier counter

__device__ __forceinline__ float to_tf32(float x) {
    float y;
    asm("cvt.rna.tf32.f32 %0, %1;" : "=f"(y) : "f"(x));
    return y;
}

__device__ __forceinline__ void mma_tf32(float d[4], const unsigned a[4], const unsigned b[2]) {
    asm volatile("mma.sync.aligned.m16n8k8.row.col.f32.tf32.tf32.f32 "
                 "{%0,%1,%2,%3}, {%4,%5,%6,%7}, {%8,%9}, {%0,%1,%2,%3};"
                 : "+f"(d[0]), "+f"(d[1]), "+f"(d[2]), "+f"(d[3])
                 : "r"(a[0]), "r"(a[1]), "r"(a[2]), "r"(a[3]),
                   "r"(b[0]), "r"(b[1]));
}

__device__ __forceinline__ void cp16(unsigned dst, const float* src) {
    asm volatile("cp.async.cg.shared.global [%0], [%1], 16;" :: "r"(dst), "l"(src));
}
__device__ __forceinline__ void cp_commit() {
    asm volatile("cp.async.commit_group;" ::: "memory");
}

// ---------------------------------------------------------------------------
// prep: tf32-round hiddens + init_carry, zero grid counter
// ---------------------------------------------------------------------------
__global__ void prep(const float* __restrict__ hiddens,
                     const float* __restrict__ init_carry) {
    size_t i0 = (size_t)blockIdx.x * blockDim.x + threadIdx.x;
    size_t stride = (size_t)gridDim.x * blockDim.x;
    size_t n = (size_t)TT * BB * DD;
    for (size_t i = i0; i < n; i += stride)
        g_hid32[i] = to_tf32(hiddens[i]);
    for (size_t i = i0; i < (size_t)BB * DD; i += stride)
        g_ic32[i] = to_tf32(init_carry[i]);
    if (i0 == 0) g_ctr = 0u;
}

// ---------------------------------------------------------------------------
// x_proj GEMM (tf32): C[M,N] = A[M,K]*W[K,N] + bias.  (unchanged from R2)
// ---------------------------------------------------------------------------
__global__ void gemm_xproj(const float* __restrict__ A,
                           const float* __restrict__ W,
                           const float* __restrict__ bias) {
    __shared__ float As[128 * 36];
    __shared__ float Bs[32 * 72];

    const int tid  = threadIdx.x;
    const int w    = tid >> 5;
    const int lane = tid & 31;
    const int q    = lane >> 2;
    const int tg   = lane & 3;
    const int wm   = w >> 1;
    const int wn   = w & 1;
    const int bm   = blockIdx.y * 128;
    const int bn   = blockIdx.x * 64;

    float acc[8][4];
    #pragma unroll
    for (int i = 0; i < 8; i++)
        #pragma unroll
        for (int j = 0; j < 4; j++) acc[i][j] = 0.f;

    for (int kc = 0; kc < DD; kc += 32) {
        #pragma unroll
        for (int l = 0; l < 4; l++) {
            int e  = tid + l * 256;
            int r  = e >> 3;
            int c4 = e & 7;
            float4 v = *(const float4*)&A[(size_t)(bm + r) * DD + kc + c4 * 4];
            float* dst = &As[r * 36 + c4 * 4];
            dst[0] = to_tf32(v.x); dst[1] = to_tf32(v.y);
            dst[2] = to_tf32(v.z); dst[3] = to_tf32(v.w);
        }
        #pragma unroll
        for (int l = 0; l < 2; l++) {
            int e  = tid + l * 256;
            int r  = e >> 4;
            int c4 = e & 15;
            float4 v = *(const float4*)&W[(size_t)(kc + r) * ND + bn + c4 * 4];
            float* dst = &Bs[r * 72 + c4 * 4];
            dst[0] = to_tf32(v.x); dst[1] = to_tf32(v.y);
            dst[2] = to_tf32(v.z); dst[3] = to_tf32(v.w);
        }
        __syncthreads();

        #pragma unroll
        for (int ks = 0; ks < 4; ks++) {
            const int koff = ks * 8;
            unsigned a[2][4];
            #pragma unroll
            for (int mt = 0; mt < 2; mt++) {
                int r0 = wm * 32 + mt * 16 + q;
                a[mt][0] = __float_as_uint(As[r0 * 36 + koff + tg]);
                a[mt][1] = __float_as_uint(As[(r0 + 8) * 36 + koff + tg]);
                a[mt][2] = __float_as_uint(As[r0 * 36 + koff + tg + 4]);
                a[mt][3] = __float_as_uint(As[(r0 + 8) * 36 + koff + tg + 4]);
            }
            #pragma unroll
            for (int nt = 0; nt < 4; nt++) {
                int n = wn * 32 + nt * 8 + q;
                unsigned b[2];
                b[0] = __float_as_uint(Bs[(koff + tg) * 72 + n]);
                b[1] = __float_as_uint(Bs[(koff + tg + 4) * 72 + n]);
                mma_tf32(acc[0 * 4 + nt], a[0], b);
                mma_tf32(acc[1 * 4 + nt], a[1], b);
            }
        }
        __syncthreads();
    }

    #pragma unroll
    for (int mt = 0; mt < 2; mt++) {
        int row = bm + wm * 32 + mt * 16 + q;
        #pragma unroll
        for (int nt = 0; nt < 4; nt++) {
            int col = bn + wn * 32 + nt * 8 + 2 * tg;
            float b0 = bias[col], b1 = bias[col + 1];
            float* c = acc[mt * 4 + nt];
            g_xproj[(size_t)row * ND + col]           = c[0] + b0;
            g_xproj[(size_t)row * ND + col + 1]       = c[1] + b1;
            g_xproj[(size_t)(row + 8) * ND + col]     = c[2] + b0;
            g_xproj[(size_t)(row + 8) * ND + col + 1] = c[3] + b1;
        }
    }
}

// ---------------------------------------------------------------------------
// Persistent GRU scan. grid=128, block=256 (co-resident: 1 block/SM).
// Block owns 8 d-cols (24 gate cols). W slice (24x1024 tf32, 96KB) lives in
// smem for the whole kernel. Per step: h staged via cp.async.cg (L2-only,
// double-buffered), k-split 2 across warps (4 m-tiles x 2 k-halves),
// smem reduction + fused gate epilogue, then grid barrier.
//
// smem float layout (dynamic, 174080 B):
//   [0,      24576)   Ws  [k=1024][24]
//   [24576,  41984)   Hs  2 buf x 2 half x (64*68)
//   [41984,  43520)   Red [64][24]
// ---------------------------------------------------------------------------
#define WS_F   0
#define HS_F(buf, half) (24576 + (((buf) * 2 + (half)) * 4352))
#define RED_F  41984
#define SMEM_BYTES 174080

__global__ void __launch_bounds__(256, 1)
gru_scan(const float* __restrict__ hiddens,
         const int*   __restrict__ dones,
         const float* __restrict__ init_carry,
         const float* __restrict__ W_h,
         const float* __restrict__ b_hn,
         float* __restrict__ out) {
    extern __shared__ float smem[];
    __shared__ unsigned char sdone[2][64];

    const int tid  = threadIdx.x;
    const int w    = tid >> 5;
    const int lane = tid & 31;
    const int q    = lane >> 2;
    const int tg   = lane & 3;
    const int mt   = w & 3;        // m-tile (16 batch rows)
    const int kh   = w >> 2;       // k-half (512 each)
    const int d0   = blockIdx.x * 8;

    float* Ws  = smem + WS_F;
    float* Red = smem + RED_F;
    const unsigned hs_base = (unsigned)__cvta_generic_to_shared(smem);

    // ---- one-time: load + convert W slice [1024 k][24 cols] ----
    for (int idx = tid; idx < 24576; idx += 256) {
        int k  = idx / 24;
        int c  = idx - k * 24;
        int g  = c >> 3;
        int di = c & 7;
        Ws[k * 24 + c] = to_tf32(W_h[(size_t)k * ND + g * DD + d0 + di]);
    }
    if (tid < 64) sdone[0][tid] = (dones[tid] != 0) ? 1 : 0;
    __syncthreads();

    const float bh0 = b_hn[d0 + ((tid * 2) & 7)];
    const float bh1 = b_hn[d0 + ((tid * 2 + 1) & 7)];

    for (int t = 0; t < TT; t++) {
        const int par = t & 1;
        const unsigned char* sd = sdone[par];
        const float* hsrc32 = (t == 0) ? g_ic32 : g_h32[par];
        const float* hsrcx  = (t == 0) ? init_carry : g_h[par];
        float* hnext   = g_h[par ^ 1];
        float* hnext32 = g_h32[par ^ 1];

        // ---- prefetch next-step dones + epilogue operands (long-latency) ----
        int dnext = 0;
        if (tid < 64 && t + 1 < TT) dnext = dones[(t + 1) * BB + tid];

        float xr[2], xz[2], xn[2], he[2];
        #pragma unroll
        for (int pi = 0; pi < 2; pi++) {
            int pp = tid * 2 + pi;
            int b  = pp >> 3;
            int di = pp & 7;
            int d  = d0 + di;
            size_t tb = (size_t)t * BB + b;
            xr[pi] = g_xproj[tb * ND + d];
            xz[pi] = g_xproj[tb * ND + DD + d];
            xn[pi] = g_xproj[tb * ND + 2 * DD + d];
            he[pi] = sd[b] ? hiddens[tb * DD + d] : hsrcx[(size_t)b * DD + d];
        }

        // ---- stage iter 0 ----
        {
            #pragma unroll
            for (int l = 0; l < 8; l++) {
                int e    = l * 256 + tid;
                int half = e >> 10;
                int rr   = (e >> 4) & 63;
                int c4   = e & 15;
                const float* src = sd[rr] ? &g_hid32[((size_t)t * BB + rr) * DD]
                                          : &hsrc32[(size_t)rr * DD];
                src += half * 512 + c4 * 4;
                unsigned dst = hs_base + (HS_F(0, half) + rr * 68 + c4 * 4) * 4;
                cp16(dst, src);
            }
            cp_commit();
        }

        float acc[3][4];
        #pragma unroll
        for (int i = 0; i < 3; i++)
            #pragma unroll
            for (int j = 0; j < 4; j++) acc[i][j] = 0.f;

        // ---- k loop: 8 iterations of 64-k chunks per half ----
        for (int it = 0; it < 8; it++) {
            if (it < 7) {
                #pragma unroll
                for (int l = 0; l < 8; l++) {
                    int e    = l * 256 + tid;
                    int half = e >> 10;
                    int rr   = (e >> 4) & 63;
                    int c4   = e & 15;
                    const float* src = sd[rr] ? &g_hid32[((size_t)t * BB + rr) * DD]
                                              : &hsrc32[(size_t)rr * DD];
                    src += half * 512 + (it + 1) * 64 + c4 * 4;
                    unsigned dst = hs_base +
                        (HS_F((it + 1) & 1, half) + rr * 68 + c4 * 4) * 4;
                    cp16(dst, src);
                }
                cp_commit();
                asm volatile("cp.async.wait_group 1;" ::: "memory");
            } else {
                asm volatile("cp.async.wait_group 0;" ::: "memory");
            }
            __syncthreads();

            const float* hchunk = smem + HS_F(it & 1, kh);
            const int kbase = kh * 512 + it * 64;

            #pragma unroll
            for (int ks = 0; ks < 8; ks++) {
                const int koff = ks * 8;
                unsigned a[4];
                const float* hrow = hchunk + (mt * 16 + q) * 68 + koff;
                a[0] = __float_as_uint(hrow[tg]);
                a[1] = __float_as_uint(hrow[8 * 68 + tg]);
                a[2] = __float_as_uint(hrow[tg + 4]);
                a[3] = __float_as_uint(hrow[8 * 68 + tg + 4]);

                const float* wr0 = Ws + (kbase + koff + tg) * 24 + q;
                const float* wr1 = wr0 + 4 * 24;
                #pragma unroll
                for (int nt = 0; nt < 3; nt++) {
                    unsigned b[2];
                    b[0] = __float_as_uint(wr0[nt * 8]);
                    b[1] = __float_as_uint(wr1[nt * 8]);
                    mma_tf32(acc[nt], a, b);
                }
            }
            __syncthreads();
        }

        // ---- reduce k-halves ----
        if (kh == 1) {
            #pragma unroll
            for (int nt = 0; nt < 3; nt++) {
                int base = (mt * 16 + q) * 24 + nt * 8 + 2 * tg;
                Red[base]            = acc[nt][0];
                Red[base + 1]        = acc[nt][1];
                Red[base + 8 * 24]     = acc[nt][2];
                Red[base + 8 * 24 + 1] = acc[nt][3];
            }
        }
        if (tid < 64 && t + 1 < TT) sdone[par ^ 1][tid] = (dnext != 0) ? 1 : 0;
        __syncthreads();
        if (kh == 0) {
            #pragma unroll
            for (int nt = 0; nt < 3; nt++) {
                int base = (mt * 16 + q) * 24 + nt * 8 + 2 * tg;
                Red[base]            += acc[nt][0];
                Red[base + 1]        += acc[nt][1];
                Red[base + 8 * 24]     += acc[nt][2];
                Red[base + 8 * 24 + 1] += acc[nt][3];
            }
        }
        __syncthreads();

        // ---- gate epilogue: 2 (b,d) pairs per thread ----
        #pragma unroll
        for (int pi = 0; pi < 2; pi++) {
            int pp = tid * 2 + pi;
            int b  = pp >> 3;
            int di = pp & 7;
            int d  = d0 + di;
            const float* rb = &Red[b * 24];

            float r = 1.f / (1.f + __expf(-(xr[pi] + rb[di])));
            float z = 1.f / (1.f + __expf(-(xz[pi] + rb[8 + di])));
            float n = tanhf(xn[pi] + r * (rb[16 + di] + (pi ? bh1 : bh0)));
            float hn = (1.f - z) * n + z * he[pi];

            size_t bd = (size_t)b * DD + d;
            hnext[bd]   = hn;
            hnext32[bd] = to_tf32(hn);
            size_t base = ((size_t)t * BB + b) * DD + d;
            out[(size_t)BB * DD + base] = hn;
            if (t == TT - 1) out[bd] = hn;
        }

        // ---- grid barrier ----
        __threadfence();
        __syncthreads();
        if (tid == 0) {
            unsigned target = (unsigned)(t + 1) * NBLK;
            asm volatile("red.release.gpu.global.add.u32 [%0], %1;"
                         :: "l"(&g_ctr), "r"(1u) : "memory");
            unsigned v;
            do {
                asm volatile("ld.acquire.gpu.global.u32 %0, [%1];"
                             : "=r"(v) : "l"(&g_ctr) : "memory");
            } while (v < target);
        }
        __syncthreads();
    }
}

// ---------------------------------------------------------------------------
extern "C" void kernel_launch(void* const* d_in, const int* in_sizes, int n_in,
                              void* d_out, int out_size) {
    const float* ins        = (const float*)d_in[0];
    const float* hiddens    = (const float*)d_in[1];
    const int*   dones      = (const int*)d_in[2];
    const float* init_carry = (const float*)d_in[3];
    const float* W_i        = (const float*)d_in[4];
    const float* W_h        = (const float*)d_in[5];
    const float* b_i        = (const float*)d_in[6];
    const float* b_hn       = (const float*)d_in[7];
    float* out = (float*)d_out;

    static int smem_set = 0;
    if (!smem_set) {
        cudaFuncSetAttribute(gru_scan, cudaFuncAttributeMaxDynamicSharedMemorySize,
                             SMEM_BYTES);
        smem_set = 1;
    }

    prep<<<2048, 256>>>(hiddens, init_carry);

    dim3 grid_gemm(ND / 64, MM / 128);   // 48 x 128
    gemm_xproj<<<grid_gemm, 256>>>(ins, W_i, b_i);

    gru_scan<<<NBLK, 256, SMEM_BYTES>>>(hiddens, dones, init_carry, W_h, b_hn, out);
}

// round 6
// speedup vs baseline: 7.5841x; 1.6004x over previous
#include <cuda_runtime.h>
#include <math.h>
#include <stdint.h>

#define TT 256
#define BB 64
#define DD 1024
#define ND 3072          // 3*D
#define MM (TT*BB)       // 16384
#define NBLK 128

// ---------------- device scratch (no cudaMalloc allowed) -------------------
__device__ __align__(16) float  g_xproj[(size_t)MM * ND];   // [T*B, 3D]
__device__ __align__(16) float  g_ins32[(size_t)MM * DD];   // tf32-rounded ins
__device__ __align__(16) float  g_Wi32[(size_t)DD * ND];    // tf32-rounded W_i
__device__ __align__(16) float  g_hx[2][BB * DD];           // exact h_eff ping-pong
__device__ float4               g_hf[2][BB * DD / 4];       // frag-ordered tf32 h ping-pong
__device__ unsigned             g_ctr;                      // grid barrier counter

__device__ __forceinline__ float to_tf32(float x) {
    float y;
    asm("cvt.rna.tf32.f32 %0, %1;" : "=f"(y) : "f"(x));
    return y;
}

__device__ __forceinline__ void mma_au(float d[4], const unsigned a[4],
                                       unsigned b0, unsigned b1) {
    asm volatile("mma.sync.aligned.m16n8k8.row.col.f32.tf32.tf32.f32 "
                 "{%0,%1,%2,%3}, {%4,%5,%6,%7}, {%8,%9}, {%0,%1,%2,%3};"
                 : "+f"(d[0]), "+f"(d[1]), "+f"(d[2]), "+f"(d[3])
                 : "r"(a[0]), "r"(a[1]), "r"(a[2]), "r"(a[3]),
                   "r"(b0), "r"(b1));
}

__device__ __forceinline__ void mma_f4(float d[4], const float4& a, const float2& b) {
    unsigned av[4] = {__float_as_uint(a.x), __float_as_uint(a.y),
                      __float_as_uint(a.z), __float_as_uint(a.w)};
    mma_au(d, av, __float_as_uint(b.x), __float_as_uint(b.y));
}

__device__ __forceinline__ void cp16(const void* smem_dst, const float* src) {
    unsigned d = (unsigned)__cvta_generic_to_shared(smem_dst);
    asm volatile("cp.async.cg.shared.global [%0], [%1], 16;" :: "r"(d), "l"(src));
}
__device__ __forceinline__ void cp_commit() {
    asm volatile("cp.async.commit_group;" ::: "memory");
}

// frag-order offset (floats) of element h[b][k] within one g_hf buffer:
// layout [ks(128)][mt(4)][lane(32)][reg(4)]
__device__ __forceinline__ int frag_off(int b, int k) {
    int mt = b >> 4, r = b & 15, q = r & 7, rh = r >> 3;
    int ks = k >> 3, kk = k & 7, tg = kk & 3, khf = kk >> 2;
    return (((ks * 4 + mt) * 32) + (q * 4 + tg)) * 4 + (rh + 2 * khf);
}

// ---------------------------------------------------------------------------
// prep: tf32-round ins + W_i; build step-0 h (done-masked) exact + frag; ctr=0
// ---------------------------------------------------------------------------
__global__ void prep(const float* __restrict__ ins,
                     const float* __restrict__ W_i,
                     const float* __restrict__ hiddens,
                     const int*   __restrict__ dones,
                     const float* __restrict__ init_carry) {
    size_t i0 = (size_t)blockIdx.x * blockDim.x + threadIdx.x;
    size_t stride = (size_t)gridDim.x * blockDim.x;

    const float4* s1 = (const float4*)ins;
    float4* d1 = (float4*)g_ins32;
    for (size_t i = i0; i < (size_t)MM * DD / 4; i += stride) {
        float4 v = s1[i];
        v.x = to_tf32(v.x); v.y = to_tf32(v.y);
        v.z = to_tf32(v.z); v.w = to_tf32(v.w);
        d1[i] = v;
    }
    const float4* s2 = (const float4*)W_i;
    float4* d2 = (float4*)g_Wi32;
    for (size_t i = i0; i < (size_t)DD * ND / 4; i += stride) {
        float4 v = s2[i];
        v.x = to_tf32(v.x); v.y = to_tf32(v.y);
        v.z = to_tf32(v.z); v.w = to_tf32(v.w);
        d2[i] = v;
    }
    for (size_t i = i0; i < (size_t)BB * DD; i += stride) {
        int b = (int)(i >> 10), d = (int)(i & 1023);
        float v = dones[b] ? hiddens[i] : init_carry[i];
        g_hx[0][i] = v;
        ((float*)g_hf[0])[frag_off(b, d)] = to_tf32(v);
    }
    if (i0 == 0) g_ctr = 0u;
}

// ---------------------------------------------------------------------------
// x_proj GEMM: C = g_ins32 * g_Wi32 + b_i.  128x128 tile, BK=32, cp.async
// double-buffered. 256 thr = 8 warps (2 wm x 4 wn), warp tile 64x32.
// ---------------------------------------------------------------------------
#define GA_ST 4608   // 128*36 floats per A stage
#define GB_ST 4224   // 32*132 floats per B stage
#define GEMM_SMEM ((2*GA_ST + 2*GB_ST) * 4)

__global__ void __launch_bounds__(256, 1)
gemm_xproj(const float* __restrict__ bias) {
    extern __shared__ float sm[];
    float* As = sm;
    float* Bs = sm + 2 * GA_ST;

    const int tid  = threadIdx.x;
    const int w    = tid >> 5, lane = tid & 31;
    const int q    = lane >> 2, tg = lane & 3;
    const int wm   = w >> 2, wn = w & 3;
    const int bm   = blockIdx.y * 128;
    const int bn   = blockIdx.x * 128;

    float acc[16][4];
    #pragma unroll
    for (int i = 0; i < 16; i++)
        #pragma unroll
        for (int j = 0; j < 4; j++) acc[i][j] = 0.f;

    // stage loader
    #define LOAD_STAGE(st, kc)                                                  \
    {                                                                           \
        _Pragma("unroll")                                                       \
        for (int l = 0; l < 4; l++) {                                           \
            int e = tid + l * 256; int r = e >> 3, c4 = e & 7;                  \
            cp16(&As[(st) * GA_ST + r * 36 + c4 * 4],                           \
                 &g_ins32[(size_t)(bm + r) * DD + (kc) + c4 * 4]);              \
        }                                                                       \
        _Pragma("unroll")                                                       \
        for (int l = 0; l < 4; l++) {                                           \
            int e = tid + l * 256; int r = e >> 5, c4 = e & 31;                 \
            cp16(&Bs[(st) * GB_ST + r * 132 + c4 * 4],                          \
                 &g_Wi32[(size_t)((kc) + r) * ND + bn + c4 * 4]);               \
        }                                                                       \
        cp_commit();                                                            \
    }

    LOAD_STAGE(0, 0)

    for (int itk = 0; itk < DD / 32; itk++) {
        if (itk + 1 < DD / 32) {
            LOAD_STAGE((itk + 1) & 1, (itk + 1) * 32)
            asm volatile("cp.async.wait_group 1;" ::: "memory");
        } else {
            asm volatile("cp.async.wait_group 0;" ::: "memory");
        }
        __syncthreads();

        const float* as = &As[(itk & 1) * GA_ST];
        const float* bs = &Bs[(itk & 1) * GB_ST];

        #pragma unroll
        for (int ks = 0; ks < 4; ks++) {
            const int koff = ks * 8;
            unsigned a[4][4];
            #pragma unroll
            for (int mt = 0; mt < 4; mt++) {
                int r0 = wm * 64 + mt * 16 + q;
                a[mt][0] = __float_as_uint(as[r0 * 36 + koff + tg]);
                a[mt][1] = __float_as_uint(as[(r0 + 8) * 36 + koff + tg]);
                a[mt][2] = __float_as_uint(as[r0 * 36 + koff + tg + 4]);
                a[mt][3] = __float_as_uint(as[(r0 + 8) * 36 + koff + tg + 4]);
            }
            #pragma unroll
            for (int nt = 0; nt < 4; nt++) {
                int n = wn * 32 + nt * 8 + q;
                unsigned b0 = __float_as_uint(bs[(koff + tg) * 132 + n]);
                unsigned b1 = __float_as_uint(bs[(koff + tg + 4) * 132 + n]);
                #pragma unroll
                for (int mt = 0; mt < 4; mt++)
                    mma_au(acc[mt * 4 + nt], a[mt], b0, b1);
            }
        }
        __syncthreads();
    }

    #pragma unroll
    for (int mt = 0; mt < 4; mt++) {
        int row = bm + wm * 64 + mt * 16 + q;
        #pragma unroll
        for (int nt = 0; nt < 4; nt++) {
            int col = bn + wn * 32 + nt * 8 + 2 * tg;
            float2 bb = *(const float2*)&bias[col];
            float* c = acc[mt * 4 + nt];
            float2 v0 = make_float2(c[0] + bb.x, c[1] + bb.y);
            float2 v1 = make_float2(c[2] + bb.x, c[3] + bb.y);
            *(float2*)&g_xproj[(size_t)row * ND + col] = v0;
            *(float2*)&g_xproj[(size_t)(row + 8) * ND + col] = v1;
        }
    }
}

// ---------------------------------------------------------------------------
// Persistent GRU scan. grid=128 (1/SM), block=256. Block owns 8 d-cols.
// W_h slice frag-ordered in smem (96KB). A-frags: direct LDG.128 (L2-only)
// from frag-ordered g_hf ping-pong, 3-deep software pipeline. k-split 8
// across warps, 4-slab smem reduction, float2 gate epilogue (writes next
// step's done-masked h in both exact and frag-tf32 form). Grid barrier/step.
//
// smem floats: Wf [ksg=128][nt=3][lane=32][2] = 24576 ; Red 4*64*24 = 6144
// ---------------------------------------------------------------------------
#define SCAN_SMEM ((24576 + 6144) * 4)

__global__ void __launch_bounds__(256, 1)
gru_scan(const float* __restrict__ hiddens,
         const int*   __restrict__ dones,
         const float* __restrict__ W_h,
         const float* __restrict__ b_hn,
         float* __restrict__ out) {
    extern __shared__ float smem[];
    float* Wf  = smem;             // 24576 floats
    float* Red = smem + 24576;     // 6144 floats

    const int tid  = threadIdx.x;
    const int w    = tid >> 5;
    const int lane = tid & 31;
    const int q    = lane >> 2;
    const int tg   = lane & 3;
    const int d0   = blockIdx.x * 8;
    const int ksg0 = w * 16;             // warp's first k-group (k-split 8)

    // ---- one-time: build frag-ordered W (tf32) ----
    for (int idx = tid; idx < 24576; idx += 256) {
        int hh = idx & 1, p = idx >> 1;
        int ln = p & 31, rest = p >> 5;
        int nt = rest % 3, ksg = rest / 3;
        int qq = ln >> 2, tt = ln & 3;
        int k  = ksg * 8 + tt + hh * 4;
        Wf[idx] = to_tf32(W_h[(size_t)k * ND + nt * DD + d0 + qq]);
    }
    __syncthreads();

    // epilogue-fixed indices: thread owns (b=pb, d=pd, pd+1)
    const int pb = tid >> 2;
    const int pd = d0 + ((tid * 2) & 7);
    const float bh0 = b_hn[pd], bh1 = b_hn[pd + 1];
    const int fo0 = frag_off(pb, pd);
    const int fo1 = frag_off(pb, pd + 1);

    for (int t = 0; t < TT; t++) {
        const int par = t & 1;

        // ---- early loads for epilogue (latency hidden under k-loop) ----
        size_t tb = (size_t)t * BB + pb;
        float2 xr = *(const float2*)&g_xproj[tb * ND + pd];
        float2 xz = *(const float2*)&g_xproj[tb * ND + DD + pd];
        float2 xn = *(const float2*)&g_xproj[tb * ND + 2 * DD + pd];
        float2 he = __ldcg((const float2*)&g_hx[par][pb * DD + pd]);
        float2 hv = make_float2(0.f, 0.f);
        int dn = 0;
        if (t + 1 < TT) {
            hv = *(const float2*)&hiddens[((size_t)(t + 1) * BB + pb) * DD + pd];
            dn = dones[(t + 1) * BB + pb];
        }

        // ---- k loop: 16 k-groups per warp, A-frag LDG pipeline depth 3 ----
        const float4* hf = g_hf[par];
        float4 pre[3][4];
        #pragma unroll
        for (int i = 0; i < 3; i++)
            #pragma unroll
            for (int mt = 0; mt < 4; mt++)
                pre[i][mt] = __ldcg(&hf[((ksg0 + i) * 4 + mt) * 32 + lane]);

        float acc[12][4];
        #pragma unroll
        for (int i = 0; i < 12; i++)
            #pragma unroll
            for (int j = 0; j < 4; j++) acc[i][j] = 0.f;

        const float2* Wf2 = (const float2*)Wf;
        #pragma unroll
        for (int it = 0; it < 16; it++) {
            const int slot = it % 3;
            float2 bv0 = Wf2[((ksg0 + it) * 3 + 0) * 32 + lane];
            float2 bv1 = Wf2[((ksg0 + it) * 3 + 1) * 32 + lane];
            float2 bv2 = Wf2[((ksg0 + it) * 3 + 2) * 32 + lane];
            #pragma unroll
            for (int mt = 0; mt < 4; mt++) {
                mma_f4(acc[mt * 3 + 0], pre[slot][mt], bv0);
                mma_f4(acc[mt * 3 + 1], pre[slot][mt], bv1);
                mma_f4(acc[mt * 3 + 2], pre[slot][mt], bv2);
            }
            if (it + 3 < 16) {
                #pragma unroll
                for (int mt = 0; mt < 4; mt++)
                    pre[slot][mt] = __ldcg(&hf[((ksg0 + it + 3) * 4 + mt) * 32 + lane]);
            }
        }

        // ---- reduce 8 warp partials -> 4 slabs ----
        float* slab = &Red[(w & 3) * 1536];
        if (w >= 4) {
            #pragma unroll
            for (int tI = 0; tI < 12; tI++) {
                int mt = tI / 3, nt = tI - mt * 3;
                int base = (mt * 16 + q) * 24 + nt * 8 + 2 * tg;
                slab[base]           = acc[tI][0];
                slab[base + 1]       = acc[tI][1];
                slab[base + 192]     = acc[tI][2];
                slab[base + 193]     = acc[tI][3];
            }
        }
        __syncthreads();
        if (w < 4) {
            #pragma unroll
            for (int tI = 0; tI < 12; tI++) {
                int mt = tI / 3, nt = tI - mt * 3;
                int base = (mt * 16 + q) * 24 + nt * 8 + 2 * tg;
                slab[base]       += acc[tI][0];
                slab[base + 1]   += acc[tI][1];
                slab[base + 192] += acc[tI][2];
                slab[base + 193] += acc[tI][3];
            }
        }
        __syncthreads();

        // ---- gate epilogue (2 adjacent d per thread) ----
        {
            const int di = (tid * 2) & 7;
            float s0r = 0.f, s0z = 0.f, s0n = 0.f;
            float s1r = 0.f, s1z = 0.f, s1n = 0.f;
            #pragma unroll
            for (int s = 0; s < 4; s++) {
                const float* rb = &Red[s * 1536 + pb * 24];
                s0r += rb[di];      s1r += rb[di + 1];
                s0z += rb[8 + di];  s1z += rb[8 + di + 1];
                s0n += rb[16 + di]; s1n += rb[16 + di + 1];
            }

            float r0 = 1.f / (1.f + __expf(-(xr.x + s0r)));
            float z0 = 1.f / (1.f + __expf(-(xz.x + s0z)));
            float n0 = tanhf(xn.x + r0 * (s0n + bh0));
            float h0 = (1.f - z0) * n0 + z0 * he.x;

            float r1 = 1.f / (1.f + __expf(-(xr.y + s1r)));
            float z1 = 1.f / (1.f + __expf(-(xz.y + s1z)));
            float n1 = tanhf(xn.y + r1 * (s1n + bh1));
            float h1 = (1.f - z1) * n1 + z1 * he.y;

            *(float2*)&out[(size_t)BB * DD + tb * DD + pd] = make_float2(h0, h1);
            if (t == TT - 1)
                *(float2*)&out[(size_t)pb * DD + pd] = make_float2(h0, h1);

            // next-step h_eff (done-masked), exact + frag-tf32
            float v0 = dn ? hv.x : h0;
            float v1 = dn ? hv.y : h1;
            *(float2*)&g_hx[par ^ 1][pb * DD + pd] = make_float2(v0, v1);
            float* hfn = (float*)g_hf[par ^ 1];
            hfn[fo0] = to_tf32(v0);
            hfn[fo1] = to_tf32(v1);
        }

        // ---- grid barrier ----
        __threadfence();
        __syncthreads();
        if (tid == 0) {
            atomicAdd(&g_ctr, 1u);
            const unsigned target = (unsigned)(t + 1) * NBLK;
            unsigned v;
            do {
                asm volatile("ld.acquire.gpu.global.u32 %0, [%1];"
                             : "=r"(v) : "l"(&g_ctr) : "memory");
            } while (v < target);
        }
        __syncthreads();
    }
}

// ---------------------------------------------------------------------------
extern "C" void kernel_launch(void* const* d_in, const int* in_sizes, int n_in,
                              void* d_out, int out_size) {
    const float* ins        = (const float*)d_in[0];
    const float* hiddens    = (const float*)d_in[1];
    const int*   dones      = (const int*)d_in[2];
    const float* init_carry = (const float*)d_in[3];
    const float* W_i        = (const float*)d_in[4];
    const float* W_h        = (const float*)d_in[5];
    const float* b_i        = (const float*)d_in[6];
    const float* b_hn       = (const float*)d_in[7];
    float* out = (float*)d_out;

    static int attr_set = 0;
    if (!attr_set) {
        cudaFuncSetAttribute(gemm_xproj, cudaFuncAttributeMaxDynamicSharedMemorySize,
                             GEMM_SMEM);
        cudaFuncSetAttribute(gru_scan, cudaFuncAttributeMaxDynamicSharedMemorySize,
                             SCAN_SMEM);
        attr_set = 1;
    }

    prep<<<2048, 256>>>(ins, W_i, hiddens, dones, init_carry);

    dim3 grid_gemm(ND / 128, MM / 128);   // 24 x 128
    gemm_xproj<<<grid_gemm, 256, GEMM_SMEM>>>(b_i);

    gru_scan<<<NBLK, 256, SCAN_SMEM>>>(hiddens, dones, W_h, b_hn, out);
}